// round 13
// baseline (speedup 1.0000x reference)
#include <cuda_runtime.h>
#include <cstdint>

#define TT 1024
#define DPAD 2080                     // padded diag count (prefetch overrun room)
#define BN 16
#define BIGS 1e10f
#define NCOST 132                     // producer CTAs; dp CTAs are 132..147
#define NBAND 15                      // tile anti-diagonal bands (8x8 tiles)

// anti-diagonal-major cost: element (i,j) at [b][(i+j)*TT + i]  (~136 MB)
__device__ float g_diag[(size_t)BN * DPAD * TT];
__device__ float g_sq[2][BN][TT];
__device__ int   g_done[BN][NBAND];   // completed tiles per (batch, band)

__device__ __forceinline__ int ld_acq(const int* p) {
    int v; asm volatile("ld.global.acquire.gpu.b32 %0, [%1];" : "=r"(v) : "l"(p));
    return v;
}
__device__ __forceinline__ int bandcnt(int k) { return k <= 7 ? k + 1 : 15 - k; }

// squared norms of every row of x (w=0) and y (w=1); block (0,0) also resets
// the output scalar and the tile-completion counters (stream-ordered before
// fused_kernel, so this is race-free and replay-deterministic).
__global__ void sq_kernel(const float* __restrict__ x, const float* __restrict__ y,
                          float* __restrict__ out) {
    int b = blockIdx.x, w = blockIdx.y, r = threadIdx.x;
    if (b == 0 && w == 0) {
        if (r == 0) out[0] = 0.0f;
        if (r < BN * NBAND) ((int*)g_done)[r] = 0;
    }
    const float* p = (w ? y : x) + ((size_t)(b * TT + r)) * 64;
    float s = 0.0f;
#pragma unroll
    for (int c = 0; c < 64; c += 4) {
        float4 v = *(const float4*)(p + c);
        s += v.x * v.x + v.y * v.y + v.z * v.z + v.w * v.w;
    }
    g_sq[w][b][r] = s;
}

// Fused producer/consumer kernel, grid = 148 (wave-1 resident).
// CTAs 0..131: cost tiles in band order, publish per-(batch,band) counters.
// CTAs 132..147: wavefront DTW, slack-1 pipelined handoff (shfl/LDS latency
// hidden one step ahead), gated per 32-step block on needed cost bands.
__global__ void __launch_bounds__(256, 1) fused_kernel(const float* __restrict__ x,
                                                       const float* __restrict__ y,
                                                       float* __restrict__ out) {
    __shared__ __align__(16) float sraw[4672];
    int bid = blockIdx.x;
    int tid = threadIdx.x;

    if (bid < NCOST) {
        // ================= cost producer role =================
        float (*Xs)[20]  = (float(*)[20])sraw;               // [128][20]
        float (*Yt)[132] = (float(*)[132])(sraw + 2560);     // [16][132]
        float (*S)[132]  = (float(*)[132])sraw;              // [32][132] overlay
        int tx = tid & 15, ty = tid >> 4;
        int wid = tid >> 5, lane = tid & 31;

        for (int T = bid; T < 64 * BN; T += NCOST) {
            // decode band-ordered tile index -> (batch b, tile it, jt)
            int kband = 0, pre = 0;
            for (;;) {
                int c = BN * bandcnt(kband);
                if (T < pre + c) break;
                pre += c; ++kband;
            }
            int rr = T - pre, cnt = bandcnt(kband);
            int b = rr / cnt, m = rr % cnt;
            int it = (kband <= 7) ? m : (kband - 7 + m);
            int jt = kband - it;

            __syncthreads();          // smem free from previous tile

            const float* xb = x + ((size_t)(b * TT + it * 128)) * 64;
            const float* yb = y + ((size_t)(b * TT + jt * 128)) * 64;

            float acc[8][8];
#pragma unroll
            for (int r = 0; r < 8; ++r)
#pragma unroll
                for (int c = 0; c < 8; ++c) acc[r][c] = 0.0f;

            for (int kc = 0; kc < 64; kc += 16) {
#pragma unroll
                for (int q = 0; q < 2; ++q) {
                    int idx = tid + q * 256;
                    int row = idx >> 2;
                    int kq  = (idx & 3) << 2;
                    float4 v = *(const float4*)(xb + (size_t)row * 64 + kc + kq);
                    *(float4*)&Xs[row][kq] = v;
                    float4 wv = *(const float4*)(yb + (size_t)row * 64 + kc + kq);
                    Yt[kq + 0][row] = wv.x;
                    Yt[kq + 1][row] = wv.y;
                    Yt[kq + 2][row] = wv.z;
                    Yt[kq + 3][row] = wv.w;
                }
                __syncthreads();

#pragma unroll
                for (int k4 = 0; k4 < 16; k4 += 4) {
                    float4 av[8];
#pragma unroll
                    for (int r = 0; r < 8; ++r) av[r] = *(const float4*)&Xs[ty * 8 + r][k4];
#pragma unroll
                    for (int kk = 0; kk < 4; ++kk) {
                        float4 b0 = *(const float4*)&Yt[k4 + kk][tx * 8];
                        float4 b1 = *(const float4*)&Yt[k4 + kk][tx * 8 + 4];
#pragma unroll
                        for (int r = 0; r < 8; ++r) {
                            float a = (kk == 0) ? av[r].x : (kk == 1) ? av[r].y
                                     : (kk == 2) ? av[r].z : av[r].w;
                            acc[r][0] = fmaf(a, b0.x, acc[r][0]);
                            acc[r][1] = fmaf(a, b0.y, acc[r][1]);
                            acc[r][2] = fmaf(a, b0.z, acc[r][2]);
                            acc[r][3] = fmaf(a, b0.w, acc[r][3]);
                            acc[r][4] = fmaf(a, b1.x, acc[r][4]);
                            acc[r][5] = fmaf(a, b1.y, acc[r][5]);
                            acc[r][6] = fmaf(a, b1.z, acc[r][6]);
                            acc[r][7] = fmaf(a, b1.w, acc[r][7]);
                        }
                    }
                }
                __syncthreads();
            }

            int r0 = it * 128, c0 = jt * 128;
            int cbase = c0 + tx * 8;
            float y2[8];
#pragma unroll
            for (int c = 0; c < 8; ++c) y2[c] = g_sq[1][b][cbase + c];

            float* gd = g_diag + (size_t)b * DPAD * TT;

            for (int k = 0; k < 4; ++k) {
                __syncthreads();
                if ((ty >> 2) == k) {
                    int rl0 = (ty & 3) * 8;
#pragma unroll
                    for (int r = 0; r < 8; ++r) {
                        int i = r0 + k * 32 + rl0 + r;
                        float x2 = g_sq[0][b][i];
                        float4 o0, o1;
                        o0.x = x2 + y2[0] - 2.0f * acc[r][0];
                        o0.y = x2 + y2[1] - 2.0f * acc[r][1];
                        o0.z = x2 + y2[2] - 2.0f * acc[r][2];
                        o0.w = x2 + y2[3] - 2.0f * acc[r][3];
                        o1.x = x2 + y2[4] - 2.0f * acc[r][4];
                        o1.y = x2 + y2[5] - 2.0f * acc[r][5];
                        o1.z = x2 + y2[6] - 2.0f * acc[r][6];
                        o1.w = x2 + y2[7] - 2.0f * acc[r][7];
                        *(float4*)&S[rl0 + r][tx * 8]     = o0;
                        *(float4*)&S[rl0 + r][tx * 8 + 4] = o1;
                    }
                }
                __syncthreads();
                int i0 = r0 + k * 32;
                int d0 = i0 + c0;
                for (int dl = wid; dl < 32 + 128 - 1; dl += 8) {
                    int rl = lane;
                    int c  = dl - rl;
                    if ((unsigned)c < 128u) {
                        gd[(size_t)(d0 + dl) * TT + i0 + rl] = S[rl][c];
                    }
                }
            }

            __syncthreads();
            if (tid == 0) { __threadfence(); atomicAdd(&g_done[b][kband], 1); }
        }
    } else {
        // ========== dp consumer role (slack-1 pipelined handoff) ==========
        float (*ring)[128] = (float(*)[128])sraw;   // ring[w] read; ring[w+1] written
        int b = bid - NCOST;
        int w = tid >> 5, l = tid & 31;

        if (tid < 128) ring[0][tid] = BIGS;

        float* rin  = ring[w];
        float* rout = ring[w + 1];
        const int* donep = g_done[b];

        const float* ld = g_diag + ((size_t)b * DPAD + 128 * w) * TT + 128 * w + 4 * l;

        float cur0 = BIGS, cur1 = BIGS, cur2 = BIGS, cur3 = BIGS;
        float Cv0 = (tid == 0) ? 0.0f : BIGS;
        float Cv1 = BIGS, Cv2 = BIGS, Cv3 = BIGS;
        float res = 0.0f;
        float hA  = BIGS;               // pipelined top value for the CURRENT step
        int   tl  = 0;
        int   j0  = -4 * l;
        bool  p0 = (l == 0), p31 = (l == 31);
        int   chk = -1;                 // highest band verified complete

        float4 Dq[16];                  // 16-step-deep prefetch (literal-indexed)
        int sb = 5 * w;                 // 160-step warp skew
        __syncthreads();

        for (int blk = 0; blk < 71; ++blk) {
            int lb = blk - sb;
            if (lb >= 0 && lb < 36) {
                // gate: prefetch window this block touches diags <= 128w+tl+47
                int kb = (128 * w + tl + 47) >> 7;
                if (kb > 14) kb = 14;
                while (chk < kb) {
                    int nb = chk + 1;
                    int need = bandcnt(nb);
                    while (ld_acq(&donep[nb]) < need) { }
                    chk = nb;
                }

                if (lb == 0) {          // prime prefetch + handoff pipeline
#pragma unroll
                    for (int q = 0; q < 16; ++q) { Dq[q] = *(const float4*)ld; ld += TT; }
                    hA = p0 ? rin[0] : BIGS;    // value for step tl=0 (col 0 / invalid)
                }

                if (lb >= 4 && lb <= 31) {
                    // interior: every cell valid
#pragma unroll
                    for (int k = 0; k < 32; ++k) {
                        float4 D = Dq[k & 15];
                        Dq[k & 15] = *(const float4*)ld;   // prefetch step tl+16
                        ld += TT;

                        float A0 = hA, A1 = cur0, A2 = cur1, A3 = cur2;
                        cur0 = D.x + fminf(fminf(A0, cur0), Cv0);
                        cur1 = D.y + fminf(fminf(A1, cur1), Cv1);
                        cur2 = D.z + fminf(fminf(A2, cur2), Cv2);
                        cur3 = D.w + fminf(fminf(A3, cur3), Cv3);
                        Cv0 = A0; Cv1 = A1; Cv2 = A2; Cv3 = A3;
                        if (p31) rout[(tl + 1) & 127] = cur3;

                        // refill pipeline for step tl+1 (latency hidden 1 step)
                        float nb2 = rin[(tl + 1) & 127];           // uniform LDS, col tl+1
                        float sh  = __shfl_up_sync(0xffffffffu, cur3, 1);
                        hA = p0 ? nb2 : sh;
                        ++tl;
                    }
                    j0 += 32;
                } else {
                    // edge: guarded body
#pragma unroll
                    for (int k = 0; k < 32; ++k) {
                        float4 D = Dq[k & 15];
                        Dq[k & 15] = *(const float4*)ld;
                        ld += TT;

                        float A0 = hA, A1 = cur0, A2 = cur1, A3 = cur2;
                        bool v0 = (unsigned)(j0)     < (unsigned)TT;
                        bool v1 = (unsigned)(j0 - 1) < (unsigned)TT;
                        bool v2 = (unsigned)(j0 - 2) < (unsigned)TT;
                        bool v3 = (unsigned)(j0 - 3) < (unsigned)TT;

                        float n0 = D.x + fminf(fminf(A0, cur0), Cv0);
                        float n1 = D.y + fminf(fminf(A1, cur1), Cv1);
                        float n2 = D.z + fminf(fminf(A2, cur2), Cv2);
                        float n3 = D.w + fminf(fminf(A3, cur3), Cv3);
                        cur0 = v0 ? n0 : BIGS;
                        cur1 = v1 ? n1 : BIGS;
                        cur2 = v2 ? n2 : BIGS;
                        cur3 = v3 ? n3 : BIGS;
                        if (v3) res = cur3;      // last valid = R[row, 1023]

                        Cv0 = A0; Cv1 = A1; Cv2 = A2; Cv3 = A3;
                        if (p31 && v3) rout[(tl + 1) & 127] = cur3;

                        float nb2 = rin[(tl + 1) & 127];
                        float sh  = __shfl_up_sync(0xffffffffu, cur3, 1);
                        hA = p0 ? nb2 : sh;
                        ++tl; ++j0;
                    }
                }
            }
            __syncthreads();
        }

        if (tid == 255) atomicAdd(out, res);   // warp 7 lane 31 q3 = R[1023,1023]
    }
}

extern "C" void kernel_launch(void* const* d_in, const int* in_sizes, int n_in,
                              void* d_out, int out_size) {
    const float* x = (const float*)d_in[0];
    const float* y = (const float*)d_in[1];
    float* out = (float*)d_out;

    sq_kernel<<<dim3(BN, 2), TT>>>(x, y, out);
    fused_kernel<<<NCOST + BN, 256>>>(x, y, out);
}

// round 14
// speedup vs baseline: 1.3827x; 1.3827x over previous
#include <cuda_runtime.h>
#include <cstdint>

#define TT 1024
#define DPAD 2080                     // padded diag count (prefetch overrun room)
#define BN 16
#define BIGS 1e10f
#define NCOST 132                     // producer CTAs; dp CTAs are 132..147
#define NBAND 15                      // tile anti-diagonal bands (8x8 tiles)

// anti-diagonal-major cost: element (i,j) at [b][(i+j)*TT + i]  (~136 MB)
__device__ float g_diag[(size_t)BN * DPAD * TT];
__device__ float g_sq[2][BN][TT];
__device__ int   g_done[BN][NBAND];   // completed tiles per (batch, band)

__device__ __forceinline__ int ld_acq(const int* p) {
    int v; asm volatile("ld.global.acquire.gpu.b32 %0, [%1];" : "=r"(v) : "l"(p));
    return v;
}
__device__ __forceinline__ int bandcnt(int k) { return k <= 7 ? k + 1 : 15 - k; }

// squared norms of every row of x (w=0) and y (w=1); block (0,0) also resets
// the output scalar and the tile-completion counters (stream-ordered before
// fused_kernel, so this is race-free and replay-deterministic).
__global__ void sq_kernel(const float* __restrict__ x, const float* __restrict__ y,
                          float* __restrict__ out) {
    int b = blockIdx.x, w = blockIdx.y, r = threadIdx.x;
    if (b == 0 && w == 0) {
        if (r == 0) out[0] = 0.0f;
        if (r < BN * NBAND) ((int*)g_done)[r] = 0;
    }
    const float* p = (w ? y : x) + ((size_t)(b * TT + r)) * 64;
    float s = 0.0f;
#pragma unroll
    for (int c = 0; c < 64; c += 4) {
        float4 v = *(const float4*)(p + c);
        s += v.x * v.x + v.y * v.y + v.z * v.z + v.w * v.w;
    }
    g_sq[w][b][r] = s;
}

// Extract component k (literal under full unroll) from float4 rq[8]
#define RQC(k) ((k & 3) == 0 ? rq[(k) >> 2].x : (k & 3) == 1 ? rq[(k) >> 2].y \
               : (k & 3) == 2 ? rq[(k) >> 2].z : rq[(k) >> 2].w)

// Fused producer/consumer kernel, grid = 148 (wave-1 resident).
// CTAs 0..131: cost tiles in band order, publish per-(batch,band) counters.
// CTAs 132..147: wavefront DTW (R12 body on an MIO diet: lane0-private
// boundary preload instead of a per-step broadcast shfl; float2-batched
// ring writes), gated per 32-step block on the needed cost bands.
__global__ void __launch_bounds__(256, 1) fused_kernel(const float* __restrict__ x,
                                                       const float* __restrict__ y,
                                                       float* __restrict__ out) {
    __shared__ __align__(16) float sraw[4672];
    int bid = blockIdx.x;
    int tid = threadIdx.x;

    if (bid < NCOST) {
        // ================= cost producer role =================
        float (*Xs)[20]  = (float(*)[20])sraw;               // [128][20]
        float (*Yt)[132] = (float(*)[132])(sraw + 2560);     // [16][132]
        float (*S)[132]  = (float(*)[132])sraw;              // [32][132] overlay
        int tx = tid & 15, ty = tid >> 4;
        int wid = tid >> 5, lane = tid & 31;

        for (int T = bid; T < 64 * BN; T += NCOST) {
            // decode band-ordered tile index -> (batch b, tile it, jt)
            int kband = 0, pre = 0;
            for (;;) {
                int c = BN * bandcnt(kband);
                if (T < pre + c) break;
                pre += c; ++kband;
            }
            int rr = T - pre, cnt = bandcnt(kband);
            int b = rr / cnt, m = rr % cnt;
            int it = (kband <= 7) ? m : (kband - 7 + m);
            int jt = kband - it;

            __syncthreads();          // smem free from previous tile

            const float* xb = x + ((size_t)(b * TT + it * 128)) * 64;
            const float* yb = y + ((size_t)(b * TT + jt * 128)) * 64;

            float acc[8][8];
#pragma unroll
            for (int r = 0; r < 8; ++r)
#pragma unroll
                for (int c = 0; c < 8; ++c) acc[r][c] = 0.0f;

            for (int kc = 0; kc < 64; kc += 16) {
#pragma unroll
                for (int q = 0; q < 2; ++q) {
                    int idx = tid + q * 256;
                    int row = idx >> 2;
                    int kq  = (idx & 3) << 2;
                    float4 v = *(const float4*)(xb + (size_t)row * 64 + kc + kq);
                    *(float4*)&Xs[row][kq] = v;
                    float4 wv = *(const float4*)(yb + (size_t)row * 64 + kc + kq);
                    Yt[kq + 0][row] = wv.x;
                    Yt[kq + 1][row] = wv.y;
                    Yt[kq + 2][row] = wv.z;
                    Yt[kq + 3][row] = wv.w;
                }
                __syncthreads();

#pragma unroll
                for (int k4 = 0; k4 < 16; k4 += 4) {
                    float4 av[8];
#pragma unroll
                    for (int r = 0; r < 8; ++r) av[r] = *(const float4*)&Xs[ty * 8 + r][k4];
#pragma unroll
                    for (int kk = 0; kk < 4; ++kk) {
                        float4 b0 = *(const float4*)&Yt[k4 + kk][tx * 8];
                        float4 b1 = *(const float4*)&Yt[k4 + kk][tx * 8 + 4];
#pragma unroll
                        for (int r = 0; r < 8; ++r) {
                            float a = (kk == 0) ? av[r].x : (kk == 1) ? av[r].y
                                     : (kk == 2) ? av[r].z : av[r].w;
                            acc[r][0] = fmaf(a, b0.x, acc[r][0]);
                            acc[r][1] = fmaf(a, b0.y, acc[r][1]);
                            acc[r][2] = fmaf(a, b0.z, acc[r][2]);
                            acc[r][3] = fmaf(a, b0.w, acc[r][3]);
                            acc[r][4] = fmaf(a, b1.x, acc[r][4]);
                            acc[r][5] = fmaf(a, b1.y, acc[r][5]);
                            acc[r][6] = fmaf(a, b1.z, acc[r][6]);
                            acc[r][7] = fmaf(a, b1.w, acc[r][7]);
                        }
                    }
                }
                __syncthreads();
            }

            int r0 = it * 128, c0 = jt * 128;
            int cbase = c0 + tx * 8;
            float y2[8];
#pragma unroll
            for (int c = 0; c < 8; ++c) y2[c] = g_sq[1][b][cbase + c];

            float* gd = g_diag + (size_t)b * DPAD * TT;

            for (int k = 0; k < 4; ++k) {
                __syncthreads();
                if ((ty >> 2) == k) {
                    int rl0 = (ty & 3) * 8;
#pragma unroll
                    for (int r = 0; r < 8; ++r) {
                        int i = r0 + k * 32 + rl0 + r;
                        float x2 = g_sq[0][b][i];
                        float4 o0, o1;
                        o0.x = x2 + y2[0] - 2.0f * acc[r][0];
                        o0.y = x2 + y2[1] - 2.0f * acc[r][1];
                        o0.z = x2 + y2[2] - 2.0f * acc[r][2];
                        o0.w = x2 + y2[3] - 2.0f * acc[r][3];
                        o1.x = x2 + y2[4] - 2.0f * acc[r][4];
                        o1.y = x2 + y2[5] - 2.0f * acc[r][5];
                        o1.z = x2 + y2[6] - 2.0f * acc[r][6];
                        o1.w = x2 + y2[7] - 2.0f * acc[r][7];
                        *(float4*)&S[rl0 + r][tx * 8]     = o0;
                        *(float4*)&S[rl0 + r][tx * 8 + 4] = o1;
                    }
                }
                __syncthreads();
                int i0 = r0 + k * 32;
                int d0 = i0 + c0;
                for (int dl = wid; dl < 32 + 128 - 1; dl += 8) {
                    int rl = lane;
                    int c  = dl - rl;
                    if ((unsigned)c < 128u) {
                        gd[(size_t)(d0 + dl) * TT + i0 + rl] = S[rl][c];
                    }
                }
            }

            __syncthreads();
            if (tid == 0) { __threadfence(); atomicAdd(&g_done[b][kband], 1); }
        }
    } else {
        // ========== dp consumer role (MIO-diet R12 body) ==========
        float (*ring)[128] = (float(*)[128])sraw;   // ring[w] read; ring[w+1] written
        int b = bid - NCOST;
        int w = tid >> 5, l = tid & 31;

        if (tid < 128) ring[0][tid] = BIGS;

        float* rin  = ring[w];
        float* rout = ring[w + 1];
        const int* donep = g_done[b];

        const float* ld = g_diag + ((size_t)b * DPAD + 128 * w) * TT + 128 * w + 4 * l;

        float cur0 = BIGS, cur1 = BIGS, cur2 = BIGS, cur3 = BIGS;
        float Cv0 = (tid == 0) ? 0.0f : BIGS;
        float Cv1 = BIGS, Cv2 = BIGS, Cv3 = BIGS;
        float res = 0.0f;
        float hS  = BIGS;               // lane31: cur3 of the previous step
        int   tl  = 0;
        int   j0  = -4 * l;
        bool  p0 = (l == 0), p31 = (l == 31);
        int   chk = -1;                 // highest band verified complete

        float4 Dq[16];                  // 16-step-deep prefetch (literal-indexed)
        int sb = 5 * w;                 // 160-step warp skew
        __syncthreads();

        for (int blk = 0; blk < 71; ++blk) {
            int lb = blk - sb;
            if (lb >= 0 && lb < 36) {
                // gate: prefetch window this block touches diags <= 128w+tl+47
                int kb = (128 * w + tl + 47) >> 7;
                if (kb > 14) kb = 14;
                while (chk < kb) {
                    int nb = chk + 1;
                    int need = bandcnt(nb);
                    while (ld_acq(&donep[nb]) < need) { }
                    chk = nb;
                }

                if (lb == 0) {          // prime 16-deep float4 prefetch
#pragma unroll
                    for (int q = 0; q < 16; ++q) { Dq[q] = *(const float4*)ld; ld += TT; }
                }
                // lane 0 preloads this block's 32 boundary values (slots
                // tl..tl+31, col c at slot c&127; tl0 mult of 32 -> aligned)
                float4 rq[8];
                if (p0) {
                    int base = tl & 127;
#pragma unroll
                    for (int i = 0; i < 8; ++i)
                        rq[i] = *(const float4*)&rin[base + 4 * i];
                } else {
#pragma unroll
                    for (int i = 0; i < 8; ++i)
                        rq[i] = make_float4(BIGS, BIGS, BIGS, BIGS);
                }

                if (lb >= 4 && lb <= 31) {
                    // interior: every cell valid
#pragma unroll
                    for (int k = 0; k < 32; ++k) {
                        float4 D = Dq[k & 15];
                        Dq[k & 15] = *(const float4*)ld;   // prefetch step tl+16
                        ld += TT;

                        float top = __shfl_up_sync(0xffffffffu, cur3, 1);
                        float A0 = p0 ? RQC(k) : top;
                        float A1 = cur0, A2 = cur1, A3 = cur2;
                        cur0 = D.x + fminf(fminf(A0, cur0), Cv0);
                        cur1 = D.y + fminf(fminf(A1, cur1), Cv1);
                        cur2 = D.z + fminf(fminf(A2, cur2), Cv2);
                        cur3 = D.w + fminf(fminf(A3, cur3), Cv3);
                        Cv0 = A0; Cv1 = A1; Cv2 = A2; Cv3 = A3;
                        // ring: slot = col & 127; write {step tl-1, step tl}
                        // pair at even steps (base tl&127 even -> aligned)
                        if (k & 1) hS = cur3;
                        else if (p31) *(float2*)&rout[tl & 127] = make_float2(hS, cur3);
                        ++tl;
                    }
                    j0 += 32;
                } else {
                    // edge: guarded body
#pragma unroll
                    for (int k = 0; k < 32; ++k) {
                        float4 D = Dq[k & 15];
                        Dq[k & 15] = *(const float4*)ld;
                        ld += TT;

                        float top = __shfl_up_sync(0xffffffffu, cur3, 1);
                        float A0 = p0 ? RQC(k) : top;
                        float A1 = cur0, A2 = cur1, A3 = cur2;
                        bool v0 = (unsigned)(j0)     < (unsigned)TT;
                        bool v1 = (unsigned)(j0 - 1) < (unsigned)TT;
                        bool v2 = (unsigned)(j0 - 2) < (unsigned)TT;
                        bool v3 = (unsigned)(j0 - 3) < (unsigned)TT;

                        float n0 = D.x + fminf(fminf(A0, cur0), Cv0);
                        float n1 = D.y + fminf(fminf(A1, cur1), Cv1);
                        float n2 = D.z + fminf(fminf(A2, cur2), Cv2);
                        float n3 = D.w + fminf(fminf(A3, cur3), Cv3);
                        cur0 = v0 ? n0 : BIGS;
                        cur1 = v1 ? n1 : BIGS;
                        cur2 = v2 ? n2 : BIGS;
                        cur3 = v3 ? n3 : BIGS;
                        if (v3) res = cur3;      // last valid = R[row, 1023]

                        Cv0 = A0; Cv1 = A1; Cv2 = A2; Cv3 = A3;
                        if (k & 1) hS = cur3;
                        else if (p31) *(float2*)&rout[tl & 127] = make_float2(hS, cur3);
                        ++tl; ++j0;
                    }
                }
            }
            __syncthreads();
        }

        if (tid == 255) atomicAdd(out, res);   // warp 7 lane 31 q3 = R[1023,1023]
    }
}

extern "C" void kernel_launch(void* const* d_in, const int* in_sizes, int n_in,
                              void* d_out, int out_size) {
    const float* x = (const float*)d_in[0];
    const float* y = (const float*)d_in[1];
    float* out = (float*)d_out;

    sq_kernel<<<dim3(BN, 2), TT>>>(x, y, out);
    fused_kernel<<<NCOST + BN, 256>>>(x, y, out);
}

// round 17
// speedup vs baseline: 1.4659x; 1.0602x over previous
#include <cuda_runtime.h>
#include <cstdint>

#define TT 1024
#define DPAD 2080                     // padded diag count (prefetch overrun room)
#define BN 16
#define BIGS 1e10f
#define NCOST 132                     // producer CTAs; dp CTAs are 132..147
#define NBAND 15                      // tile anti-diagonal bands (8x8 tiles)

// anti-diagonal-major cost: element (i,j) at [b][(i+j)*TT + i]  (~136 MB)
__device__ float g_diag[(size_t)BN * DPAD * TT];
__device__ float g_sq[2][BN][TT];
__device__ int   g_done[BN][NBAND];   // completed tiles per (batch, band)

__device__ __forceinline__ int ld_acq(const int* p) {
    int v; asm volatile("ld.global.acquire.gpu.b32 %0, [%1];" : "=r"(v) : "l"(p));
    return v;
}
__device__ __forceinline__ int bandcnt(int k) { return k <= 7 ? k + 1 : 15 - k; }

// squared norms of every row of x (w=0) and y (w=1); block (0,0) also resets
// the output scalar and the tile-completion counters (stream-ordered before
// fused_kernel, so this is race-free and replay-deterministic).
__global__ void sq_kernel(const float* __restrict__ x, const float* __restrict__ y,
                          float* __restrict__ out) {
    int b = blockIdx.x, w = blockIdx.y, r = threadIdx.x;
    if (b == 0 && w == 0) {
        if (r == 0) out[0] = 0.0f;
        if (r < BN * NBAND) ((int*)g_done)[r] = 0;
    }
    const float* p = (w ? y : x) + ((size_t)(b * TT + r)) * 64;
    float s = 0.0f;
#pragma unroll
    for (int c = 0; c < 64; c += 4) {
        float4 v = *(const float4*)(p + c);
        s += v.x * v.x + v.y * v.y + v.z * v.z + v.w * v.w;
    }
    g_sq[w][b][r] = s;
}

// Extract component k (literal under full unroll) from float4 rq[8]
#define RQC(k) ((k & 3) == 0 ? rq[(k) >> 2].x : (k & 3) == 1 ? rq[(k) >> 2].y \
               : (k & 3) == 2 ? rq[(k) >> 2].z : rq[(k) >> 2].w)

// Fused producer/consumer kernel, grid = 148 (wave-1 resident).
// CTAs 0..131: cost tiles in band order, publish per-(batch,band) counters.
// CTAs 132..147: wavefront DTW with pipelined cross-lane handoff: the shfl
// for step t+1 is issued right after cur3 is produced at step t, so its
// 26-32 cyc latency is hidden behind a full step of slack.
__global__ void __launch_bounds__(256, 1) fused_kernel(const float* __restrict__ x,
                                                       const float* __restrict__ y,
                                                       float* __restrict__ out) {
    __shared__ __align__(16) float sraw[4672];
    int bid = blockIdx.x;
    int tid = threadIdx.x;

    if (bid < NCOST) {
        // ================= cost producer role =================
        float (*Xs)[20]  = (float(*)[20])sraw;               // [128][20]
        float (*Yt)[132] = (float(*)[132])(sraw + 2560);     // [16][132]
        float (*S)[132]  = (float(*)[132])sraw;              // [32][132] overlay
        int tx = tid & 15, ty = tid >> 4;
        int wid = tid >> 5, lane = tid & 31;

        for (int T = bid; T < 64 * BN; T += NCOST) {
            // decode band-ordered tile index -> (batch b, tile it, jt)
            int kband = 0, pre = 0;
            for (;;) {
                int c = BN * bandcnt(kband);
                if (T < pre + c) break;
                pre += c; ++kband;
            }
            int rr = T - pre, cnt = bandcnt(kband);
            int b = rr / cnt, m = rr % cnt;
            int it = (kband <= 7) ? m : (kband - 7 + m);
            int jt = kband - it;

            __syncthreads();          // smem free from previous tile

            const float* xb = x + ((size_t)(b * TT + it * 128)) * 64;
            const float* yb = y + ((size_t)(b * TT + jt * 128)) * 64;

            float acc[8][8];
#pragma unroll
            for (int r = 0; r < 8; ++r)
#pragma unroll
                for (int c = 0; c < 8; ++c) acc[r][c] = 0.0f;

            for (int kc = 0; kc < 64; kc += 16) {
#pragma unroll
                for (int q = 0; q < 2; ++q) {
                    int idx = tid + q * 256;
                    int row = idx >> 2;
                    int kq  = (idx & 3) << 2;
                    float4 v = *(const float4*)(xb + (size_t)row * 64 + kc + kq);
                    *(float4*)&Xs[row][kq] = v;
                    float4 wv = *(const float4*)(yb + (size_t)row * 64 + kc + kq);
                    Yt[kq + 0][row] = wv.x;
                    Yt[kq + 1][row] = wv.y;
                    Yt[kq + 2][row] = wv.z;
                    Yt[kq + 3][row] = wv.w;
                }
                __syncthreads();

#pragma unroll
                for (int k4 = 0; k4 < 16; k4 += 4) {
                    float4 av[8];
#pragma unroll
                    for (int r = 0; r < 8; ++r) av[r] = *(const float4*)&Xs[ty * 8 + r][k4];
#pragma unroll
                    for (int kk = 0; kk < 4; ++kk) {
                        float4 b0 = *(const float4*)&Yt[k4 + kk][tx * 8];
                        float4 b1 = *(const float4*)&Yt[k4 + kk][tx * 8 + 4];
#pragma unroll
                        for (int r = 0; r < 8; ++r) {
                            float a = (kk == 0) ? av[r].x : (kk == 1) ? av[r].y
                                     : (kk == 2) ? av[r].z : av[r].w;
                            acc[r][0] = fmaf(a, b0.x, acc[r][0]);
                            acc[r][1] = fmaf(a, b0.y, acc[r][1]);
                            acc[r][2] = fmaf(a, b0.z, acc[r][2]);
                            acc[r][3] = fmaf(a, b0.w, acc[r][3]);
                            acc[r][4] = fmaf(a, b1.x, acc[r][4]);
                            acc[r][5] = fmaf(a, b1.y, acc[r][5]);
                            acc[r][6] = fmaf(a, b1.z, acc[r][6]);
                            acc[r][7] = fmaf(a, b1.w, acc[r][7]);
                        }
                    }
                }
                __syncthreads();
            }

            int r0 = it * 128, c0 = jt * 128;
            int cbase = c0 + tx * 8;
            float y2[8];
#pragma unroll
            for (int c = 0; c < 8; ++c) y2[c] = g_sq[1][b][cbase + c];

            float* gd = g_diag + (size_t)b * DPAD * TT;

            for (int k = 0; k < 4; ++k) {
                __syncthreads();
                if ((ty >> 2) == k) {
                    int rl0 = (ty & 3) * 8;
#pragma unroll
                    for (int r = 0; r < 8; ++r) {
                        int i = r0 + k * 32 + rl0 + r;
                        float x2 = g_sq[0][b][i];
                        float4 o0, o1;
                        o0.x = x2 + y2[0] - 2.0f * acc[r][0];
                        o0.y = x2 + y2[1] - 2.0f * acc[r][1];
                        o0.z = x2 + y2[2] - 2.0f * acc[r][2];
                        o0.w = x2 + y2[3] - 2.0f * acc[r][3];
                        o1.x = x2 + y2[4] - 2.0f * acc[r][4];
                        o1.y = x2 + y2[5] - 2.0f * acc[r][5];
                        o1.z = x2 + y2[6] - 2.0f * acc[r][6];
                        o1.w = x2 + y2[7] - 2.0f * acc[r][7];
                        *(float4*)&S[rl0 + r][tx * 8]     = o0;
                        *(float4*)&S[rl0 + r][tx * 8 + 4] = o1;
                    }
                }
                __syncthreads();
                int i0 = r0 + k * 32;
                int d0 = i0 + c0;
                for (int dl = wid; dl < 32 + 128 - 1; dl += 8) {
                    int rl = lane;
                    int c  = dl - rl;
                    if ((unsigned)c < 128u) {
                        gd[(size_t)(d0 + dl) * TT + i0 + rl] = S[rl][c];
                    }
                }
            }

            __syncthreads();
            if (tid == 0) { __threadfence(); atomicAdd(&g_done[b][kband], 1); }
        }
    } else {
        // ========== dp consumer role (pipelined-shfl body) ==========
        float (*ring)[128] = (float(*)[128])sraw;   // ring[w] read; ring[w+1] written
        int b = bid - NCOST;
        int w = tid >> 5, l = tid & 31;

        if (tid < 128) ring[0][tid] = BIGS;

        float* rin  = ring[w];
        float* rout = ring[w + 1];
        const int* donep = g_done[b];

        const float* ld = g_diag + ((size_t)b * DPAD + 128 * w) * TT + 128 * w + 4 * l;

        float cur0 = BIGS, cur1 = BIGS, cur2 = BIGS, cur3 = BIGS;
        float Cv0 = (tid == 0) ? 0.0f : BIGS;
        float Cv1 = BIGS, Cv2 = BIGS, Cv3 = BIGS;
        float res = 0.0f;
        float hS  = BIGS;               // lane31: cur3 of the previous step
        float hA  = BIGS;               // incoming top for CURRENT step (shfl'd last step)
        int   tl  = 0;
        int   j0  = -4 * l;
        bool  p0 = (l == 0), p31 = (l == 31);
        int   chk = -1;                 // highest band verified complete

        float4 Dq[16];                  // 16-step-deep prefetch (literal-indexed)
        int sb = 5 * w;                 // 160-step warp skew
        __syncthreads();

        for (int blk = 0; blk < 71; ++blk) {
            int lb = blk - sb;
            if (lb >= 0 && lb < 36) {
                // gate: prefetch window this block touches diags <= 128w+tl+47
                int kb = (128 * w + tl + 47) >> 7;
                if (kb > 14) kb = 14;
                while (chk < kb) {
                    int nb = chk + 1;
                    int need = bandcnt(nb);
                    while (ld_acq(&donep[nb]) < need) { }
                    chk = nb;
                }

                if (lb == 0) {          // prime 16-deep float4 prefetch
#pragma unroll
                    for (int q = 0; q < 16; ++q) { Dq[q] = *(const float4*)ld; ld += TT; }
                    hA = BIGS;          // neighbor state is all-BIGS at warp start
                }
                // lane 0 preloads this block's 32 boundary values (slots
                // tl..tl+31, col c at slot c&127; tl0 mult of 32 -> aligned)
                float4 rq[8];
                if (p0) {
                    int base = tl & 127;
#pragma unroll
                    for (int i = 0; i < 8; ++i)
                        rq[i] = *(const float4*)&rin[base + 4 * i];
                } else {
#pragma unroll
                    for (int i = 0; i < 8; ++i)
                        rq[i] = make_float4(BIGS, BIGS, BIGS, BIGS);
                }

                if (lb >= 4 && lb <= 31) {
                    // interior: every cell valid
#pragma unroll
                    for (int k = 0; k < 32; ++k) {
                        float4 D = Dq[k & 15];
                        Dq[k & 15] = *(const float4*)ld;   // prefetch step tl+16
                        ld += TT;

                        float A0 = p0 ? RQC(k) : hA;       // shfl'd LAST step (hidden)
                        float A1 = cur0, A2 = cur1, A3 = cur2;
                        cur0 = D.x + fminf(fminf(A0, cur0), Cv0);
                        cur1 = D.y + fminf(fminf(A1, cur1), Cv1);
                        cur2 = D.z + fminf(fminf(A2, cur2), Cv2);
                        cur3 = D.w + fminf(fminf(A3, cur3), Cv3);
                        hA = __shfl_up_sync(0xffffffffu, cur3, 1);  // for step tl+1
                        Cv0 = A0; Cv1 = A1; Cv2 = A2; Cv3 = A3;
                        // ring: slot = col & 127; write {step tl-1, step tl}
                        // pair at even steps (base tl&127 even -> aligned)
                        if (k & 1) hS = cur3;
                        else if (p31) *(float2*)&rout[tl & 127] = make_float2(hS, cur3);
                        ++tl;
                    }
                    j0 += 32;
                } else {
                    // edge: guarded body
#pragma unroll
                    for (int k = 0; k < 32; ++k) {
                        float4 D = Dq[k & 15];
                        Dq[k & 15] = *(const float4*)ld;
                        ld += TT;

                        float A0 = p0 ? RQC(k) : hA;
                        float A1 = cur0, A2 = cur1, A3 = cur2;
                        bool v0 = (unsigned)(j0)     < (unsigned)TT;
                        bool v1 = (unsigned)(j0 - 1) < (unsigned)TT;
                        bool v2 = (unsigned)(j0 - 2) < (unsigned)TT;
                        bool v3 = (unsigned)(j0 - 3) < (unsigned)TT;

                        float n0 = D.x + fminf(fminf(A0, cur0), Cv0);
                        float n1 = D.y + fminf(fminf(A1, cur1), Cv1);
                        float n2 = D.z + fminf(fminf(A2, cur2), Cv2);
                        float n3 = D.w + fminf(fminf(A3, cur3), Cv3);
                        cur0 = v0 ? n0 : BIGS;
                        cur1 = v1 ? n1 : BIGS;
                        cur2 = v2 ? n2 : BIGS;
                        cur3 = v3 ? n3 : BIGS;
                        hA = __shfl_up_sync(0xffffffffu, cur3, 1);  // for step tl+1
                        if (v3) res = cur3;      // last valid = R[row, 1023]

                        Cv0 = A0; Cv1 = A1; Cv2 = A2; Cv3 = A3;
                        if (k & 1) hS = cur3;
                        else if (p31) *(float2*)&rout[tl & 127] = make_float2(hS, cur3);
                        ++tl; ++j0;
                    }
                }
            }
            __syncthreads();
        }

        if (tid == 255) atomicAdd(out, res);   // warp 7 lane 31 q3 = R[1023,1023]
    }
}

extern "C" void kernel_launch(void* const* d_in, const int* in_sizes, int n_in,
                              void* d_out, int out_size) {
    const float* x = (const float*)d_in[0];
    const float* y = (const float*)d_in[1];
    float* out = (float*)d_out;

    sq_kernel<<<dim3(BN, 2), TT>>>(x, y, out);
    fused_kernel<<<NCOST + BN, 256>>>(x, y, out);
}